// round 10
// baseline (speedup 1.0000x reference)
#include <cuda_runtime.h>
#include <cstdint>

// ---------------------------------------------------------------------------
// DSS kernel: out[l,h] = Re( sum_n Wk[h,n] * exp(dtLambda[h,n] * l) )
// Fastpath (H=1024, N=64, L=2048): SINGLE fused kernel.
//   Block = 256 threads = 8 warps = (2 h) x (4 n-quarters); covers 2 h and
//   one L-half. Work identical to the 4-warp version (seeds are per
//   (h, half, pair) and each pair is seeded exactly once) — the n-split only
//   raises resident warps/SMSP, which measurement shows issue scales with.
//   Phase 1: per-(h, n-pair) constants in smem (z^1024 folded into Wk).
//   Phase 2: per warp: pipelined fast-trig seeds + TWO independent stride-64
//            real recurrences x+ = A2 x - B2 x-  (packed f32x2), NJJ=16.
//   Phase 3: 4-way smem reduction across n-quarters + transpose + f32x2 store.
// ---------------------------------------------------------------------------

#define EPS2 1e-14f   // EPS^2, EPS = 1e-7

#define FH 1024
#define FN 64
#define FL 2048
#define FNP 32          // n-pairs total
#define NPW 8           // n-pairs per warp
#define HT  2           // h per block
#define NJJ 16          // recurrence steps (each covers 2 output phases)

#define INV_2PI 0.15915494309189535f
#define PI2_HI  6.2831854820251465f
#define PI2_LO  (-1.7484556000744483e-7f)
#define INV2PI_D 0.15915494309189535
#define TWOPI_D  6.283185307179586

typedef unsigned long long u64;
#define PK(d, lo, hi)   asm("mov.b64 %0, {%1, %2};" : "=l"(d) : "f"(lo), "f"(hi))
#define UPK(lo, hi, v)  asm("mov.b64 {%0, %1}, %2;" : "=f"(lo), "=f"(hi) : "l"(v))
#define MUL2(d, a, b)   asm("mul.rn.f32x2 %0, %1, %2;" : "=l"(d) : "l"(a), "l"(b))
#define ADD2(d, a, b)   asm("add.rn.f32x2 %0, %1, %2;" : "=l"(d) : "l"(a), "l"(b))
#define FMA2(d, a, b, c) asm("fma.rn.f32x2 %0, %1, %2, %3;" : "=l"(d) : "l"(a), "l"(b), "l"(c))

// fast sin/cos with explicit Cody-Waite reduction to [-pi, pi]
__device__ __forceinline__ void fast_sincos(float th, float* s, float* c)
{
    float k = rintf(th * INV_2PI);
    float r = fmaf(-k, PI2_HI, th);
    r = fmaf(-k, PI2_LO, r);
    *s = __sinf(r);
    *c = __cosf(r);
}

// precise: reduce mult*b in double, then sincosf on the small residue
__device__ __forceinline__ void dp_sincos(float b, float mult, float* s, float* c)
{
    double th = (double)mult * (double)b;
    double k = rint(th * INV2PI_D);
    float r = (float)(th - k * TWOPI_D);
    sincosf(r, s, c);
}

// ---------------------------------------------------------------------------
// Fused kernel. Block = (htile, half): 256 threads, 8 warps.
// Warp w: h_local = w & 1, n-quarter = w >> 1 (8 n-pairs per warp).
// smem const slots per (h_local, np), each float4 (parity-packed pairs):
//   s0: (a0, a1, b0, b1)
//   s1: (wkr0, wkr1, nwki0, nwki1)    wk includes z^1024 rotation if half
//   s2: (wki0, wki1, m1r0, m1r1)      m1 = z^32
//   s3: (nm1i0, nm1i1, A1_0, A1_1)    A1 = 2 Re z^32
//   s4: (nB1_0, nB1_1, A2_0, A2_1)    B1 = e^{64a}, A2 = 2 Re z^64
//   s5: (nB2_0, nB2_1, 0, 0)          B2 = e^{128a}
// ---------------------------------------------------------------------------
__global__ void __launch_bounds__(256, 2) k_fused(
    const float* __restrict__ log_dt,
    const float* __restrict__ llnr,
    const float* __restrict__ lim,
    const float* __restrict__ W,
    float* __restrict__ out)
{
    __shared__ float4 npcs[6][HT][FNP];
    __shared__ float tile[2][2][32][33];    // [hl][nq-group][j][p]

    const int blk   = blockIdx.x;         // htile*2 + half
    const int half  = blk & 1;
    const int htile = blk >> 1;
    const int h0    = htile * HT;
    const int tid   = threadIdx.x;
    const int w     = tid >> 5;
    const int hl    = w & 1;               // h_local
    const int nh    = w >> 1;              // n-quarter (8 pairs each)
    const int p     = tid & 31;

    // ---------------- Phase 1: per-(h, np) constants (threads 0..63) ---------
    if (tid < 64) {
        const int hl1 = tid >> 5;
        const int np  = tid & 31;
        const int h   = h0 + hl1;

        float dtr = expf(log_dt[2 * h + 0]);
        float dti = expf(log_dt[2 * h + 1]);

        float a_[2], b_[2], wkr_[2], wki_[2];
        float m1r_[2], nm1i_[2], A1_[2], nB1_[2], A2_[2], nB2_[2];

#pragma unroll
        for (int par = 0; par < 2; par++) {
            int n = 2 * np + par;
            float lr = -expf(llnr[n]);
            float li = lim[n];
            float a = dtr * lr;      // < 0
            float b = dti * li;
            a_[par] = a;  b_[par] = b;

            // Wk = Wc * (exp(dtL)-1) * reciprocal_clamped(Lambda)
            float ns = fmaxf(lr * lr + li * li, EPS2);
            float rr =  lr / ns;
            float ri = -li / ns;
            float ea = expf(a), sb, cb;
            sincosf(b, &sb, &cb);
            float edr = ea * cb - 1.0f;
            float edi = ea * sb;
            float wr = W[(h * FN + n) * 2 + 0];
            float wi = W[(h * FN + n) * 2 + 1];
            float tr = wr * edr - wi * edi;
            float ti = wr * edi + wi * edr;
            float wkr = tr * rr - ti * ri;
            float wki = tr * ri + ti * rr;

            if (half) {              // fold z^1024 rotation into Wk (precise)
                float s1k, c1k;
                dp_sincos(b, 1024.0f, &s1k, &c1k);
                float e1k = expf(1024.0f * a);
                float qr = e1k * c1k, qi = e1k * s1k;
                float nwr = wkr * qr - wki * qi;
                float nwi = wkr * qi + wki * qr;
                wkr = nwr;  wki = nwi;
            }
            wkr_[par] = wkr;  wki_[par] = wki;

            // m1 = z^32 (DP-reduced angle)
            float s32, c32;
            dp_sincos(b, 32.0f, &s32, &c32);
            float e32 = expf(32.0f * a);
            float m1r = e32 * c32, m1i = e32 * s32;
            m1r_[par]  = m1r;
            nm1i_[par] = -m1i;

            float e64 = e32 * e32;                // e^{64a}
            A1_[par]  = 2.0f * m1r;
            nB1_[par] = -e64;
            A2_[par]  = 2.0f * (m1r * m1r - m1i * m1i);
            nB2_[par] = -e64 * e64;               // -e^{128a}
        }

        npcs[0][hl1][np] = make_float4(a_[0], a_[1], b_[0], b_[1]);
        npcs[1][hl1][np] = make_float4(wkr_[0], wkr_[1], -wki_[0], -wki_[1]);
        npcs[2][hl1][np] = make_float4(wki_[0], wki_[1], m1r_[0], m1r_[1]);
        npcs[3][hl1][np] = make_float4(nm1i_[0], nm1i_[1], A1_[0], A1_[1]);
        npcs[4][hl1][np] = make_float4(nB1_[0], nB1_[1], A2_[0], A2_[1]);
        npcs[5][hl1][np] = make_float4(nB2_[0], nB2_[1], 0.0f, 0.0f);
    }
    __syncthreads();

    // ---------------- Phase 2: pipelined seeds + ILP-2 recurrence ------------
    const float lm = (float)p - 64.0f;   // seed G at l = half*1024 + p - 64

    u64 acc[2 * NJJ];
#pragma unroll
    for (int j = 0; j < 2 * NJJ; j++) acc[j] = 0ULL;

    auto seeds = [&](int np, u64& cme, u64& cmo, u64& ce, u64& co,
                     u64& A2, u64& nB2) {
        float4 ab = npcs[0][hl][np];
        ulonglong2 s1 = *reinterpret_cast<const ulonglong2*>(&npcs[1][hl][np]);
        ulonglong2 s2 = *reinterpret_cast<const ulonglong2*>(&npcs[2][hl][np]);
        ulonglong2 s3 = *reinterpret_cast<const ulonglong2*>(&npcs[3][hl][np]);
        ulonglong2 s4 = *reinterpret_cast<const ulonglong2*>(&npcs[4][hl][np]);
        ulonglong2 s5 = *reinterpret_cast<const ulonglong2*>(&npcs[5][hl][np]);

        float e0 = __expf(ab.x * lm);
        float e1 = __expf(ab.y * lm);
        float s0f, c0f, s1f, c1f;
        fast_sincos(ab.z * lm, &s0f, &c0f);
        fast_sincos(ab.w * lm, &s1f, &c1f);
        u64 Er2, Ei2;
        PK(Er2, e0 * c0f, e1 * c1f);
        PK(Ei2, e0 * s0f, e1 * s1f);

        u64 Gr, Gi, t;
        MUL2(t, s1.x, Er2);  FMA2(Gr, s1.y, Ei2, t);    // wkr*Er - wki*Ei
        MUL2(t, s1.x, Ei2);  FMA2(Gi, s2.x, Er2, t);    // wkr*Ei + wki*Er

        cme = Gr;                                        // x(p-64)
        MUL2(t, s2.y, Gr);   FMA2(cmo, s3.x, Gi, t);     // Re(G*z^32): x(p-32)
        MUL2(t, s3.y, cmo);  FMA2(ce,  s4.x, cme, t);    // x(p)
        MUL2(t, s3.y, ce);   FMA2(co,  s4.x, cmo, t);    // x(p+32)
        A2  = s4.y;
        nB2 = s5.x;
    };

    auto body = [&](u64 cme, u64 cmo, u64 ce, u64 co, u64 A2, u64 nB2) {
#pragma unroll
        for (int jj = 0; jj < NJJ; jj++) {
            ADD2(acc[2 * jj],     acc[2 * jj],     ce);
            ADD2(acc[2 * jj + 1], acc[2 * jj + 1], co);
            u64 te, to;
            MUL2(te, ce, A2);  FMA2(te, cme, nB2, te);
            MUL2(to, co, A2);  FMA2(to, cmo, nB2, to);
            cme = ce;  ce = te;
            cmo = co;  co = to;
        }
    };

    const int np0 = nh * NPW;            // this warp's 8 n-pairs

    u64 cme, cmo, ce, co, A2, nB2;
    seeds(np0, cme, cmo, ce, co, A2, nB2);

#pragma unroll 1
    for (int np = np0; np < np0 + NPW - 1; np++) {
        u64 ncme, ncmo, nce, nco, nA2, nnB2;
        seeds(np + 1, ncme, ncmo, nce, nco, nA2, nnB2);  // hidden under body
        body(cme, cmo, ce, co, A2, nB2);
        cme = ncme;  cmo = ncmo;  ce = nce;  co = nco;
        A2 = nA2;  nB2 = nnB2;
    }
    body(cme, cmo, ce, co, A2, nB2);                     // epilogue

    // ---------------- Phase 3: 4-way reduction + transpose + stores ----------
    // Group g = nh>>1 owns tile[hl][g]; within a group, nh&1==0 writes,
    // nh&1==1 adds. Final store sums the two groups.
    {
        float (*t)[33] = tile[hl][nh >> 1];
        if ((nh & 1) == 0) {
#pragma unroll
            for (int j = 0; j < 2 * NJJ; j++) {
                float lo, hi;
                UPK(lo, hi, acc[j]);
                t[j][p] = lo + hi;
            }
        }
    }
    __syncthreads();
    {
        float (*t)[33] = tile[hl][nh >> 1];
        if ((nh & 1) == 1) {
#pragma unroll
            for (int j = 0; j < 2 * NJJ; j++) {
                float lo, hi;
                UPK(lo, hi, acc[j]);
                t[j][p] += lo + hi;
            }
        }
    }
    __syncthreads();

    {
        const int kk = tid >> 5;        // 0..7
        const int pp = tid & 31;        // l phase within 32
        const int l0 = half << 10;
#pragma unroll
        for (int k = kk; k < 2 * NJJ; k += 8) {
            float2 v = make_float2(tile[0][0][k][pp] + tile[0][1][k][pp],
                                   tile[1][0][k][pp] + tile[1][1][k][pp]);
            *reinterpret_cast<float2*>(out + (size_t)(l0 + (k << 5) + pp) * FH + h0) = v;
        }
    }
}

// ---------------------------------------------------------------------------
// Generic fallback (correct for any shape; slow).
// ---------------------------------------------------------------------------
__global__ void k_generic(const float* __restrict__ log_dt,
                          const float* __restrict__ llnr,
                          const float* __restrict__ lim,
                          const float* __restrict__ W,
                          float* __restrict__ out,
                          int H, int N, int L)
{
    int idx = blockIdx.x * blockDim.x + threadIdx.x;
    if (idx >= L * H) return;
    int l = idx / H, h = idx - l * H;
    float dtr = expf(log_dt[2 * h + 0]);
    float dti = expf(log_dt[2 * h + 1]);
    float fl = (float)l;
    float sum = 0.0f;
    for (int n = 0; n < N; n++) {
        float lr = -expf(llnr[n]);
        float li = lim[n];
        float a = dtr * lr, b = dti * li;
        float ns = fmaxf(lr * lr + li * li, EPS2);
        float rr = lr / ns, ri = -li / ns;
        float ea = expf(a), sb, cb;
        sincosf(b, &sb, &cb);
        float edr = ea * cb - 1.0f, edi = ea * sb;
        float wr = W[(h * N + n) * 2 + 0], wi = W[(h * N + n) * 2 + 1];
        float tr = wr * edr - wi * edi, ti = wr * edi + wi * edr;
        float wkr = tr * rr - ti * ri, wki = tr * ri + ti * rr;
        float el = expf(a * fl), sl, cl;
        sincosf(b * fl, &sl, &cl);
        sum += wkr * (el * cl) - wki * (el * sl);
    }
    out[idx] = sum;
}

// ---------------------------------------------------------------------------
extern "C" void kernel_launch(void* const* d_in, const int* in_sizes, int n_in,
                              void* d_out, int out_size)
{
    const float* log_dt = (const float*)d_in[0];   // (H,2)
    const float* llnr   = (const float*)d_in[1];   // (N,)
    const float* lim    = (const float*)d_in[2];   // (N,)
    const float* W      = (const float*)d_in[3];   // (H,N,2)
    float* out = (float*)d_out;

    int H = in_sizes[0] / 2;
    int N = in_sizes[1];
    int L = out_size / H;

    if (H == FH && N == FN && L == FL) {
        k_fused<<<(FH / HT) * 2, 256>>>(log_dt, llnr, lim, W, out);
    } else {
        int tot = L * H;
        k_generic<<<(tot + 255) / 256, 256>>>(log_dt, llnr, lim, W, out, H, N, L);
    }
}

// round 11
// speedup vs baseline: 1.0814x; 1.0814x over previous
#include <cuda_runtime.h>
#include <cstdint>

// ---------------------------------------------------------------------------
// DSS kernel: out[l,h] = Re( sum_n Wk[h,n] * exp(dtLambda[h,n] * l) )
// Fastpath (H=1024, N=64, L=2048): SINGLE fused kernel.
//   Packed f32x2 latency measured ~16+ cyc -> the jj loop needs chain-level
//   ILP, not warps. This version processes TWO n-pairs per jj iteration:
//   4 independent mul-fma recurrence chains + tree-summed accumulate,
//   12 packed ops per jj covering 4 n (same 3 ops/point as before, 2x ILP).
//   Block = 128 thr = 4 warps = (2 h) x (2 n-halves); grid = 1024.
// ---------------------------------------------------------------------------

#define EPS2 1e-14f   // EPS^2, EPS = 1e-7

#define FH 1024
#define FN 64
#define FL 2048
#define FNP 32          // n-pairs total
#define NPW 16          // n-pairs per warp
#define HT  2           // h per block
#define NJJ 16          // recurrence steps (each covers 2 output phases)

#define INV_2PI 0.15915494309189535f
#define PI2_HI  6.2831854820251465f
#define PI2_LO  (-1.7484556000744483e-7f)
#define INV2PI_D 0.15915494309189535
#define TWOPI_D  6.283185307179586

typedef unsigned long long u64;
#define PK(d, lo, hi)   asm("mov.b64 %0, {%1, %2};" : "=l"(d) : "f"(lo), "f"(hi))
#define UPK(lo, hi, v)  asm("mov.b64 {%0, %1}, %2;" : "=f"(lo), "=f"(hi) : "l"(v))
#define MUL2(d, a, b)   asm("mul.rn.f32x2 %0, %1, %2;" : "=l"(d) : "l"(a), "l"(b))
#define ADD2(d, a, b)   asm("add.rn.f32x2 %0, %1, %2;" : "=l"(d) : "l"(a), "l"(b))
#define FMA2(d, a, b, c) asm("fma.rn.f32x2 %0, %1, %2, %3;" : "=l"(d) : "l"(a), "l"(b), "l"(c))

// fast sin/cos with explicit Cody-Waite reduction to [-pi, pi]
__device__ __forceinline__ void fast_sincos(float th, float* s, float* c)
{
    float k = rintf(th * INV_2PI);
    float r = fmaf(-k, PI2_HI, th);
    r = fmaf(-k, PI2_LO, r);
    *s = __sinf(r);
    *c = __cosf(r);
}

// precise: reduce mult*b in double, then sincosf on the small residue
__device__ __forceinline__ void dp_sincos(float b, float mult, float* s, float* c)
{
    double th = (double)mult * (double)b;
    double k = rint(th * INV2PI_D);
    float r = (float)(th - k * TWOPI_D);
    sincosf(r, s, c);
}

// ---------------------------------------------------------------------------
// Fused kernel. Block = (htile, half): 128 threads, 4 warps.
// Warp w: h_local = w & 1, n-half = w >> 1 (16 n-pairs per warp).
// smem const slots per (h_local, np), each float4 (parity-packed pairs):
//   s0: (a0, a1, b0, b1)
//   s1: (wkr0, wkr1, nwki0, nwki1)    wk includes z^1024 rotation if half
//   s2: (wki0, wki1, m1r0, m1r1)      m1 = z^32
//   s3: (nm1i0, nm1i1, A1_0, A1_1)    A1 = 2 Re z^32
//   s4: (nB1_0, nB1_1, A2_0, A2_1)    B1 = e^{64a}, A2 = 2 Re z^64
//   s5: (nB2_0, nB2_1, 0, 0)          B2 = e^{128a}
// ---------------------------------------------------------------------------
struct ChainState { u64 cme, cmo, ce, co, A2, nB2; };

__global__ void __launch_bounds__(128, 4) k_fused(
    const float* __restrict__ log_dt,
    const float* __restrict__ llnr,
    const float* __restrict__ lim,
    const float* __restrict__ W,
    float* __restrict__ out)
{
    __shared__ float4 npcs[6][HT][FNP];
    __shared__ float tileA[32][33];
    __shared__ float tileB[32][33];

    const int blk   = blockIdx.x;         // htile*2 + half
    const int half  = blk & 1;
    const int htile = blk >> 1;
    const int h0    = htile * HT;
    const int tid   = threadIdx.x;
    const int w     = tid >> 5;
    const int hl    = w & 1;               // h_local
    const int nh    = w >> 1;              // n-half (16 pairs each)
    const int p     = tid & 31;

    // ---------------- Phase 1: per-(h, np) constants (threads 0..63) ---------
    if (tid < 64) {
        const int hl1 = tid >> 5;
        const int np  = tid & 31;
        const int h   = h0 + hl1;

        float dtr = expf(log_dt[2 * h + 0]);
        float dti = expf(log_dt[2 * h + 1]);

        float a_[2], b_[2], wkr_[2], wki_[2];
        float m1r_[2], nm1i_[2], A1_[2], nB1_[2], A2_[2], nB2_[2];

#pragma unroll
        for (int par = 0; par < 2; par++) {
            int n = 2 * np + par;
            float lr = -expf(llnr[n]);
            float li = lim[n];
            float a = dtr * lr;      // < 0
            float b = dti * li;
            a_[par] = a;  b_[par] = b;

            // Wk = Wc * (exp(dtL)-1) * reciprocal_clamped(Lambda)
            float ns = fmaxf(lr * lr + li * li, EPS2);
            float rr =  lr / ns;
            float ri = -li / ns;
            float ea = expf(a), sb, cb;
            sincosf(b, &sb, &cb);
            float edr = ea * cb - 1.0f;
            float edi = ea * sb;
            float wr = W[(h * FN + n) * 2 + 0];
            float wi = W[(h * FN + n) * 2 + 1];
            float tr = wr * edr - wi * edi;
            float ti = wr * edi + wi * edr;
            float wkr = tr * rr - ti * ri;
            float wki = tr * ri + ti * rr;

            if (half) {              // fold z^1024 rotation into Wk (precise)
                float s1k, c1k;
                dp_sincos(b, 1024.0f, &s1k, &c1k);
                float e1k = expf(1024.0f * a);
                float qr = e1k * c1k, qi = e1k * s1k;
                float nwr = wkr * qr - wki * qi;
                float nwi = wkr * qi + wki * qr;
                wkr = nwr;  wki = nwi;
            }
            wkr_[par] = wkr;  wki_[par] = wki;

            // m1 = z^32 (DP-reduced angle)
            float s32, c32;
            dp_sincos(b, 32.0f, &s32, &c32);
            float e32 = expf(32.0f * a);
            float m1r = e32 * c32, m1i = e32 * s32;
            m1r_[par]  = m1r;
            nm1i_[par] = -m1i;

            float e64 = e32 * e32;                // e^{64a}
            A1_[par]  = 2.0f * m1r;
            nB1_[par] = -e64;
            A2_[par]  = 2.0f * (m1r * m1r - m1i * m1i);
            nB2_[par] = -e64 * e64;               // -e^{128a}
        }

        npcs[0][hl1][np] = make_float4(a_[0], a_[1], b_[0], b_[1]);
        npcs[1][hl1][np] = make_float4(wkr_[0], wkr_[1], -wki_[0], -wki_[1]);
        npcs[2][hl1][np] = make_float4(wki_[0], wki_[1], m1r_[0], m1r_[1]);
        npcs[3][hl1][np] = make_float4(nm1i_[0], nm1i_[1], A1_[0], A1_[1]);
        npcs[4][hl1][np] = make_float4(nB1_[0], nB1_[1], A2_[0], A2_[1]);
        npcs[5][hl1][np] = make_float4(nB2_[0], nB2_[1], 0.0f, 0.0f);
    }
    __syncthreads();

    // ---------------- Phase 2: ILP-4 recurrence (2 pairs per jj) -------------
    const float lm = (float)p - 64.0f;   // seed G at l = half*1024 + p - 64

    u64 acc[2 * NJJ];
#pragma unroll
    for (int j = 0; j < 2 * NJJ; j++) acc[j] = 0ULL;

    auto seeds = [&](int np, ChainState& s) {
        float4 ab = npcs[0][hl][np];
        ulonglong2 s1 = *reinterpret_cast<const ulonglong2*>(&npcs[1][hl][np]);
        ulonglong2 s2 = *reinterpret_cast<const ulonglong2*>(&npcs[2][hl][np]);
        ulonglong2 s3 = *reinterpret_cast<const ulonglong2*>(&npcs[3][hl][np]);
        ulonglong2 s4 = *reinterpret_cast<const ulonglong2*>(&npcs[4][hl][np]);
        ulonglong2 s5 = *reinterpret_cast<const ulonglong2*>(&npcs[5][hl][np]);

        float e0 = __expf(ab.x * lm);
        float e1 = __expf(ab.y * lm);
        float s0f, c0f, s1f, c1f;
        fast_sincos(ab.z * lm, &s0f, &c0f);
        fast_sincos(ab.w * lm, &s1f, &c1f);
        u64 Er2, Ei2;
        PK(Er2, e0 * c0f, e1 * c1f);
        PK(Ei2, e0 * s0f, e1 * s1f);

        u64 Gr, Gi, t;
        MUL2(t, s1.x, Er2);  FMA2(Gr, s1.y, Ei2, t);    // wkr*Er - wki*Ei
        MUL2(t, s1.x, Ei2);  FMA2(Gi, s2.x, Er2, t);    // wkr*Ei + wki*Er

        s.cme = Gr;                                      // x(p-64)
        MUL2(t, s2.y, Gr);     FMA2(s.cmo, s3.x, Gi, t);    // x(p-32)
        MUL2(t, s3.y, s.cmo);  FMA2(s.ce,  s4.x, s.cme, t); // x(p)
        MUL2(t, s3.y, s.ce);   FMA2(s.co,  s4.x, s.cmo, t); // x(p+32)
        s.A2  = s4.y;
        s.nB2 = s5.x;
    };

    // dual-pair body: 4 independent chains + tree accumulate
    auto body2 = [&](ChainState a, ChainState b) {
#pragma unroll
        for (int jj = 0; jj < NJJ; jj++) {
            u64 se, so;
            ADD2(se, a.ce, b.ce);
            ADD2(so, a.co, b.co);
            ADD2(acc[2 * jj],     acc[2 * jj],     se);
            ADD2(acc[2 * jj + 1], acc[2 * jj + 1], so);
            u64 te1, to1, te2, to2;
            MUL2(te1, a.ce, a.A2);  FMA2(te1, a.cme, a.nB2, te1);
            MUL2(to1, a.co, a.A2);  FMA2(to1, a.cmo, a.nB2, to1);
            MUL2(te2, b.ce, b.A2);  FMA2(te2, b.cme, b.nB2, te2);
            MUL2(to2, b.co, b.A2);  FMA2(to2, b.cmo, b.nB2, to2);
            a.cme = a.ce;  a.ce = te1;
            a.cmo = a.co;  a.co = to1;
            b.cme = b.ce;  b.ce = te2;
            b.cmo = b.co;  b.co = to2;
        }
    };

    const int np0 = nh * NPW;            // this warp's 16 n-pairs

#pragma unroll 1
    for (int g = 0; g < NPW / 2; g++) {
        ChainState sA, sB;
        seeds(np0 + 2 * g,     sA);
        seeds(np0 + 2 * g + 1, sB);
        body2(sA, sB);
    }

    // ---------------- Phase 3: n-half reduction + transpose + stores ---------
    {
        float (*tile)[33] = hl ? tileB : tileA;
        if (nh == 0) {
#pragma unroll
            for (int j = 0; j < 2 * NJJ; j++) {
                float lo, hi;
                UPK(lo, hi, acc[j]);
                tile[j][p] = lo + hi;
            }
        }
    }
    __syncthreads();
    {
        float (*tile)[33] = hl ? tileB : tileA;
        if (nh == 1) {
#pragma unroll
            for (int j = 0; j < 2 * NJJ; j++) {
                float lo, hi;
                UPK(lo, hi, acc[j]);
                tile[j][p] += lo + hi;
            }
        }
    }
    __syncthreads();

    {
        const int kk = tid >> 5;        // 0..3
        const int pp = tid & 31;        // l phase within 32
        const int l0 = half << 10;
#pragma unroll
        for (int k = kk; k < 2 * NJJ; k += 4) {
            float2 v = make_float2(tileA[k][pp], tileB[k][pp]);
            *reinterpret_cast<float2*>(out + (size_t)(l0 + (k << 5) + pp) * FH + h0) = v;
        }
    }
}

// ---------------------------------------------------------------------------
// Generic fallback (correct for any shape; slow).
// ---------------------------------------------------------------------------
__global__ void k_generic(const float* __restrict__ log_dt,
                          const float* __restrict__ llnr,
                          const float* __restrict__ lim,
                          const float* __restrict__ W,
                          float* __restrict__ out,
                          int H, int N, int L)
{
    int idx = blockIdx.x * blockDim.x + threadIdx.x;
    if (idx >= L * H) return;
    int l = idx / H, h = idx - l * H;
    float dtr = expf(log_dt[2 * h + 0]);
    float dti = expf(log_dt[2 * h + 1]);
    float fl = (float)l;
    float sum = 0.0f;
    for (int n = 0; n < N; n++) {
        float lr = -expf(llnr[n]);
        float li = lim[n];
        float a = dtr * lr, b = dti * li;
        float ns = fmaxf(lr * lr + li * li, EPS2);
        float rr = lr / ns, ri = -li / ns;
        float ea = expf(a), sb, cb;
        sincosf(b, &sb, &cb);
        float edr = ea * cb - 1.0f, edi = ea * sb;
        float wr = W[(h * N + n) * 2 + 0], wi = W[(h * N + n) * 2 + 1];
        float tr = wr * edr - wi * edi, ti = wr * edi + wi * edr;
        float wkr = tr * rr - ti * ri, wki = tr * ri + ti * rr;
        float el = expf(a * fl), sl, cl;
        sincosf(b * fl, &sl, &cl);
        sum += wkr * (el * cl) - wki * (el * sl);
    }
    out[idx] = sum;
}

// ---------------------------------------------------------------------------
extern "C" void kernel_launch(void* const* d_in, const int* in_sizes, int n_in,
                              void* d_out, int out_size)
{
    const float* log_dt = (const float*)d_in[0];   // (H,2)
    const float* llnr   = (const float*)d_in[1];   // (N,)
    const float* lim    = (const float*)d_in[2];   // (N,)
    const float* W      = (const float*)d_in[3];   // (H,N,2)
    float* out = (float*)d_out;

    int H = in_sizes[0] / 2;
    int N = in_sizes[1];
    int L = out_size / H;

    if (H == FH && N == FN && L == FL) {
        k_fused<<<(FH / HT) * 2, 128>>>(log_dt, llnr, lim, W, out);
    } else {
        int tot = L * H;
        k_generic<<<(tot + 255) / 256, 256>>>(log_dt, llnr, lim, W, out, H, N, L);
    }
}